// round 4
// baseline (speedup 1.0000x reference)
#include <cuda_runtime.h>
#include <math.h>

#define N_NODES  100000
#define HID      128
#define NUM_CLS  20
#define N_EDGES  625000

// ---------------------------------------------------------------------------
// Scratch (__device__ globals; no allocation allowed)
// ---------------------------------------------------------------------------
__device__ float g_aggr[(size_t)N_NODES * HID];   // mean-aggregated neighbors
__device__ int   g_cnt[N_NODES];
__device__ int   g_off[N_NODES];
__device__ int   g_cur[N_NODES];
__device__ int   g_csr[N_EDGES];
__device__ int   g_is64;                          // 1 if edge_index is int64

// ---------------------------------------------------------------------------
// K0: detect edge dtype. int64 [2,E] layout => every odd 32-bit word is the
// zero high-half (node ids < 1e5). int32 => odd words are random edge ids.
// ---------------------------------------------------------------------------
__global__ void detect_kernel(const unsigned* __restrict__ ew) {
    unsigned acc = 0;
    for (int i = threadIdx.x; i < 1024; i += blockDim.x)
        acc |= ew[2 * i + 1];
    __shared__ unsigned s;
    if (threadIdx.x == 0) s = 0;
    __syncthreads();
    if (acc) atomicOr(&s, acc);
    __syncthreads();
    if (threadIdx.x == 0) g_is64 = (s == 0) ? 1 : 0;
}

__device__ __forceinline__ int edge_at(const unsigned* ew, int is64, int idx) {
    return is64 ? (int)ew[2 * idx] : (int)ew[idx];
}

// ---------------------------------------------------------------------------
// K1: zero counters
// ---------------------------------------------------------------------------
__global__ void zero_kernel() {
    int i = blockIdx.x * blockDim.x + threadIdx.x;
    int stride = gridDim.x * blockDim.x;
    for (int j = i; j < N_NODES; j += stride) { g_cnt[j] = 0; g_cur[j] = 0; }
}

// ---------------------------------------------------------------------------
// K2: in-degree histogram
// ---------------------------------------------------------------------------
__global__ void count_kernel(const unsigned* __restrict__ ew) {
    int e = blockIdx.x * blockDim.x + threadIdx.x;
    if (e >= N_EDGES) return;
    int is64 = g_is64;
    int dst = edge_at(ew, is64, N_EDGES + e);
    atomicAdd(&g_cnt[dst], 1);
}

// ---------------------------------------------------------------------------
// K3: exclusive prefix sum over 100K counts (single block, 1024 threads)
// ---------------------------------------------------------------------------
__global__ __launch_bounds__(1024)
void scan_kernel() {
    __shared__ int part[1024];
    const int t = threadIdx.x;
    const int per = (N_NODES + 1023) / 1024;   // 98
    const int base = t * per;
    int s = 0;
    for (int i = 0; i < per; ++i) {
        int j = base + i;
        if (j < N_NODES) s += g_cnt[j];
    }
    part[t] = s;
    __syncthreads();
    for (int off = 1; off < 1024; off <<= 1) {
        int v = (t >= off) ? part[t - off] : 0;
        __syncthreads();
        part[t] += v;
        __syncthreads();
    }
    int run = (t == 0) ? 0 : part[t - 1];
    for (int i = 0; i < per; ++i) {
        int j = base + i;
        if (j < N_NODES) { g_off[j] = run; run += g_cnt[j]; }
    }
}

// ---------------------------------------------------------------------------
// K4: fill CSR buckets with source node ids
// ---------------------------------------------------------------------------
__global__ void fill_kernel(const unsigned* __restrict__ ew) {
    int e = blockIdx.x * blockDim.x + threadIdx.x;
    if (e >= N_EDGES) return;
    int is64 = g_is64;
    int src = edge_at(ew, is64, e);
    int dst = edge_at(ew, is64, N_EDGES + e);
    int slot = g_off[dst] + atomicAdd(&g_cur[dst], 1);
    g_csr[slot] = src;
}

// ---------------------------------------------------------------------------
// K5: gather + mean. One warp per node, lane = float4 column (32x16B = row).
// No atomics: each output row has exactly one writer warp. Next-source
// prefetch pipelines the dependent idx-load -> row-load chain.
// ---------------------------------------------------------------------------
__global__ void gather_kernel(const float* __restrict__ x) {
    unsigned gtid = blockIdx.x * blockDim.x + threadIdx.x;
    unsigned n = gtid >> 5;
    int lane = threadIdx.x & 31;
    if (n >= N_NODES) return;

    int beg = g_off[n];
    int cnt = g_cnt[n];
    float4 acc = make_float4(0.f, 0.f, 0.f, 0.f);
    const float4* x4 = reinterpret_cast<const float4*>(x);

    int s = (cnt > 0) ? __ldg(&g_csr[beg]) : 0;
    for (int i = 0; i < cnt; ++i) {
        int s_next = (i + 1 < cnt) ? __ldg(&g_csr[beg + i + 1]) : 0;
        float4 v = __ldg(&x4[(size_t)s * 32 + lane]); // coalesced 512B/warp
        acc.x += v.x; acc.y += v.y; acc.z += v.z; acc.w += v.w;
        s = s_next;
    }
    float inv = 1.0f / fmaxf((float)cnt, 1.0f);
    acc.x *= inv; acc.y *= inv; acc.z *= inv; acc.w *= inv;
    reinterpret_cast<float4*>(g_aggr)[(size_t)n * 32 + lane] = acc;
}

// ---------------------------------------------------------------------------
// K6: fused GEMM + bias + row L2-norm + normed classifier.
//   A = [aggr | x]  (M=100000, K=256), B = [W_l ; W_r] (256x128)
//   h = A@B + b_l; out = l2norm_row(h) @ l2norm_col(W_cls)
// Persistent 148 blocks x 256 threads; whole B + W_cls resident in smem.
// Per-thread register tile: 8 rows x 4 cols.
// ---------------------------------------------------------------------------
#define MT 64
#define SMEM_FLOATS (256*128 + MT*256 + 128*NUM_CLS + 128 + 32)
#define SMEM_BYTES  (SMEM_FLOATS * 4)

__global__ __launch_bounds__(256, 1)
void fused_kernel(const float* __restrict__ x,
                  const float* __restrict__ W_l,
                  const float* __restrict__ b_l,
                  const float* __restrict__ W_r,
                  const float* __restrict__ W_cls,
                  float* __restrict__ out) {
    extern __shared__ float smem[];
    float* sB    = smem;                    // [256][128]
    float* sA    = sB + 256 * 128;          // [64][256]; reused as sH [64][128]
    float* sWc   = sA + MT * 256;           // [128][20]
    float* sBias = sWc + 128 * NUM_CLS;     // [128]
    float* sInvC = sBias + 128;             // [20]

    const int tid = threadIdx.x;

    for (int i = tid; i < 128 * 128 / 4; i += 256) {
        reinterpret_cast<float4*>(sB)[i] =
            reinterpret_cast<const float4*>(W_l)[i];
        reinterpret_cast<float4*>(sB + 128 * 128)[i] =
            reinterpret_cast<const float4*>(W_r)[i];
    }
    for (int i = tid; i < 128 * NUM_CLS; i += 256) sWc[i] = W_cls[i];
    if (tid < 128) sBias[tid] = b_l[tid];
    __syncthreads();
    if (tid < NUM_CLS) {
        float s = 0.f;
        for (int j = 0; j < 128; ++j) { float w = sWc[j * NUM_CLS + tid]; s += w * w; }
        sInvC[tid] = 1.0f / fmaxf(sqrtf(s), 1e-12f);
    }
    __syncthreads();

    const int tn = tid & 31;   // lane -> 4-col group
    const int tm = tid >> 5;   // warp -> 8-row group
    const int numTiles = (N_NODES + MT - 1) / MT;

    for (int tile = blockIdx.x; tile < numTiles; tile += gridDim.x) {
        const int row0 = tile * MT;

        // A tile: [64 rows][64 float4] = [aggr | x]
        for (int i = tid; i < MT * 64; i += 256) {
            int r = i >> 6, q = i & 63;
            int row = row0 + r;
            float4 v = make_float4(0.f, 0.f, 0.f, 0.f);
            if (row < N_NODES) {
                if (q < 32)
                    v = reinterpret_cast<const float4*>(g_aggr)[(size_t)row * 32 + q];
                else
                    v = reinterpret_cast<const float4*>(x)[(size_t)row * 32 + (q - 32)];
            }
            reinterpret_cast<float4*>(sA)[r * 64 + q] = v;
        }
        __syncthreads();

        float acc[8][4];
        #pragma unroll
        for (int r = 0; r < 8; ++r)
            #pragma unroll
            for (int i = 0; i < 4; ++i) acc[r][i] = 0.f;

        const float* sArow = sA + (tm * 8) * 256;
        #pragma unroll 4
        for (int k = 0; k < 256; ++k) {
            float4 b = reinterpret_cast<const float4*>(sB)[k * 32 + tn];
            #pragma unroll
            for (int r = 0; r < 8; ++r) {
                float a = sArow[r * 256 + k];   // broadcast within warp
                acc[r][0] += a * b.x;
                acc[r][1] += a * b.y;
                acc[r][2] += a * b.z;
                acc[r][3] += a * b.w;
            }
        }
        __syncthreads();  // done reading sA before reuse as sH

        // bias + row L2 norm (warp butterfly over 128 cols)
        float4 bias = reinterpret_cast<const float4*>(sBias)[tn];
        #pragma unroll
        for (int r = 0; r < 8; ++r) {
            float hx = acc[r][0] + bias.x;
            float hy = acc[r][1] + bias.y;
            float hz = acc[r][2] + bias.z;
            float hw = acc[r][3] + bias.w;
            float ss = hx * hx + hy * hy + hz * hz + hw * hw;
            #pragma unroll
            for (int off = 16; off; off >>= 1)
                ss += __shfl_xor_sync(0xffffffffu, ss, off);
            float inv = 1.0f / fmaxf(sqrtf(ss), 1e-12f);
            float4 h = make_float4(hx * inv, hy * inv, hz * inv, hw * inv);
            reinterpret_cast<float4*>(sA)[(tm * 8 + r) * 32 + tn] = h;
        }
        __syncthreads();

        // classifier: 64 rows x 20 classes
        for (int o = tid; o < MT * NUM_CLS; o += 256) {
            int r = o / NUM_CLS, c = o - r * NUM_CLS;
            int row = row0 + r;
            if (row < N_NODES) {
                const float* hrow = sA + r * 128;
                float s = 0.f;
                #pragma unroll 8
                for (int j = 0; j < 128; ++j)
                    s += hrow[j] * sWc[j * NUM_CLS + c];
                out[(size_t)row * NUM_CLS + c] = s * sInvC[c];
            }
        }
        __syncthreads();
    }
}

// ---------------------------------------------------------------------------
extern "C" void kernel_launch(void* const* d_in, const int* in_sizes, int n_in,
                              void* d_out, int out_size) {
    (void)in_sizes; (void)n_in; (void)out_size;
    const float*    x     = (const float*)d_in[0];
    const unsigned* ew    = (const unsigned*)d_in[1];  // int32 or int64 words
    const float*    W_l   = (const float*)d_in[2];
    const float*    b_l   = (const float*)d_in[3];
    const float*    W_r   = (const float*)d_in[4];
    const float*    W_cls = (const float*)d_in[5];
    float*          out   = (float*)d_out;

    detect_kernel<<<1, 256>>>(ew);
    zero_kernel<<<256, 256>>>();
    count_kernel<<<(N_EDGES + 255) / 256, 256>>>(ew);
    scan_kernel<<<1, 1024>>>();
    fill_kernel<<<(N_EDGES + 255) / 256, 256>>>(ew);

    const unsigned gthreads = (unsigned)N_NODES * 32u;
    gather_kernel<<<(gthreads + 255) / 256, 256>>>(x);

    cudaFuncSetAttribute(fused_kernel,
                         cudaFuncAttributeMaxDynamicSharedMemorySize, SMEM_BYTES);
    fused_kernel<<<148, 256, SMEM_BYTES>>>(x, W_l, b_l, W_r, W_cls, out);
}

// round 5
// speedup vs baseline: 1.2481x; 1.2481x over previous
#include <cuda_runtime.h>
#include <math.h>

#define N_NODES  100000
#define HID      128
#define NUM_CLS  20
#define N_EDGES  625000

typedef unsigned long long ull;

// ---------------------------------------------------------------------------
// Scratch (__device__ globals; no allocation allowed)
// ---------------------------------------------------------------------------
__device__ float g_aggr[(size_t)N_NODES * HID];   // mean-aggregated neighbors
__device__ int   g_cnt[N_NODES];
__device__ int   g_off[N_NODES];
__device__ int   g_cur[N_NODES];
__device__ int   g_csr[N_EDGES];
__device__ int   g_is64;                          // 1 if edge_index is int64

#define SCAN_B   512
#define SCAN_NB  ((N_NODES + SCAN_B - 1) / SCAN_B)   // 196
__device__ int   g_part[SCAN_NB];
__device__ int   g_base[SCAN_NB];

// ---------------------------------------------------------------------------
// f32x2 helpers (Blackwell packed fp32: 2 MACs/lane on the fma pipe)
// ---------------------------------------------------------------------------
__device__ __forceinline__ ull ffma2(ull a, ull b, ull c) {
    ull d;
    asm("fma.rn.f32x2 %0, %1, %2, %3;" : "=l"(d) : "l"(a), "l"(b), "l"(c));
    return d;
}
__device__ __forceinline__ ull pack2(float lo, float hi) {
    ull d; asm("mov.b64 %0, {%1, %2};" : "=l"(d) : "f"(lo), "f"(hi)); return d;
}
__device__ __forceinline__ void unpack2(ull v, float& lo, float& hi) {
    asm("mov.b64 {%0, %1}, %2;" : "=f"(lo), "=f"(hi) : "l"(v));
}

// ---------------------------------------------------------------------------
// K0: detect edge dtype. int64 [2,E] layout => every odd 32-bit word is the
// zero high-half (node ids < 1e5). int32 => odd words are random edge ids.
// ---------------------------------------------------------------------------
__global__ void detect_kernel(const unsigned* __restrict__ ew) {
    unsigned acc = 0;
    for (int i = threadIdx.x; i < 1024; i += blockDim.x)
        acc |= ew[2 * i + 1];
    __shared__ unsigned s;
    if (threadIdx.x == 0) s = 0;
    __syncthreads();
    if (acc) atomicOr(&s, acc);
    __syncthreads();
    if (threadIdx.x == 0) g_is64 = (s == 0) ? 1 : 0;
}

__device__ __forceinline__ int edge_at(const unsigned* ew, int is64, int idx) {
    return is64 ? (int)ew[2 * idx] : (int)ew[idx];
}

// ---------------------------------------------------------------------------
// K1: zero counters
// ---------------------------------------------------------------------------
__global__ void zero_kernel() {
    int i = blockIdx.x * blockDim.x + threadIdx.x;
    int stride = gridDim.x * blockDim.x;
    for (int j = i; j < N_NODES; j += stride) { g_cnt[j] = 0; g_cur[j] = 0; }
}

// ---------------------------------------------------------------------------
// K2: in-degree histogram
// ---------------------------------------------------------------------------
__global__ void count_kernel(const unsigned* __restrict__ ew) {
    int e = blockIdx.x * blockDim.x + threadIdx.x;
    if (e >= N_EDGES) return;
    int is64 = g_is64;
    int dst = edge_at(ew, is64, N_EDGES + e);
    atomicAdd(&g_cnt[dst], 1);
}

// ---------------------------------------------------------------------------
// K3a: per-block sums (196 blocks x 512 counts)
// ---------------------------------------------------------------------------
__global__ __launch_bounds__(256)
void scanA_kernel() {
    __shared__ int sh[256];
    const int b = blockIdx.x, t = threadIdx.x;
    int s = 0;
    for (int i = t; i < SCAN_B; i += 256) {
        int j = b * SCAN_B + i;
        if (j < N_NODES) s += g_cnt[j];
    }
    sh[t] = s;
    __syncthreads();
    for (int off = 128; off; off >>= 1) {
        if (t < off) sh[t] += sh[t + off];
        __syncthreads();
    }
    if (t == 0) g_part[b] = sh[0];
}

// ---------------------------------------------------------------------------
// K3b: exclusive scan of 196 block partials (single tiny block)
// ---------------------------------------------------------------------------
__global__ __launch_bounds__(256)
void scanB_kernel() {
    __shared__ int a[256];
    const int t = threadIdx.x;
    a[t] = (t < SCAN_NB) ? g_part[t] : 0;
    __syncthreads();
    for (int off = 1; off < 256; off <<= 1) {
        int v = (t >= off) ? a[t - off] : 0;
        __syncthreads();
        a[t] += v;
        __syncthreads();
    }
    if (t < SCAN_NB) g_base[t] = (t == 0) ? 0 : a[t - 1];
}

// ---------------------------------------------------------------------------
// K3c: per-block exclusive scan + base -> g_off (2 elems per thread)
// ---------------------------------------------------------------------------
__global__ __launch_bounds__(256)
void scanC_kernel() {
    __shared__ int a[256];
    const int b = blockIdx.x, t = threadIdx.x;
    const int j0 = b * SCAN_B + 2 * t;
    int c0 = (j0     < N_NODES) ? g_cnt[j0]     : 0;
    int c1 = (j0 + 1 < N_NODES) ? g_cnt[j0 + 1] : 0;
    a[t] = c0 + c1;
    __syncthreads();
    for (int off = 1; off < 256; off <<= 1) {
        int v = (t >= off) ? a[t - off] : 0;
        __syncthreads();
        a[t] += v;
        __syncthreads();
    }
    int excl = ((t == 0) ? 0 : a[t - 1]) + g_base[b];
    if (j0     < N_NODES) g_off[j0]     = excl;
    if (j0 + 1 < N_NODES) g_off[j0 + 1] = excl + c0;
}

// ---------------------------------------------------------------------------
// K4: fill CSR buckets with source node ids
// ---------------------------------------------------------------------------
__global__ void fill_kernel(const unsigned* __restrict__ ew) {
    int e = blockIdx.x * blockDim.x + threadIdx.x;
    if (e >= N_EDGES) return;
    int is64 = g_is64;
    int src = edge_at(ew, is64, e);
    int dst = edge_at(ew, is64, N_EDGES + e);
    int slot = g_off[dst] + atomicAdd(&g_cur[dst], 1);
    g_csr[slot] = src;
}

// ---------------------------------------------------------------------------
// K5: gather + mean. One warp per node, lane = float4 column (32x16B = row).
// No atomics: each output row has exactly one writer warp. Next-source
// prefetch pipelines the dependent idx-load -> row-load chain.
// ---------------------------------------------------------------------------
__global__ void gather_kernel(const float* __restrict__ x) {
    unsigned gtid = blockIdx.x * blockDim.x + threadIdx.x;
    unsigned n = gtid >> 5;
    int lane = threadIdx.x & 31;
    if (n >= N_NODES) return;

    int beg = g_off[n];
    int cnt = g_cnt[n];
    float4 acc = make_float4(0.f, 0.f, 0.f, 0.f);
    const float4* x4 = reinterpret_cast<const float4*>(x);

    int s = (cnt > 0) ? __ldg(&g_csr[beg]) : 0;
    for (int i = 0; i < cnt; ++i) {
        int s_next = (i + 1 < cnt) ? __ldg(&g_csr[beg + i + 1]) : 0;
        float4 v = __ldg(&x4[(size_t)s * 32 + lane]); // coalesced 512B/warp
        acc.x += v.x; acc.y += v.y; acc.z += v.z; acc.w += v.w;
        s = s_next;
    }
    float inv = 1.0f / fmaxf((float)cnt, 1.0f);
    acc.x *= inv; acc.y *= inv; acc.z *= inv; acc.w *= inv;
    reinterpret_cast<float4*>(g_aggr)[(size_t)n * 32 + lane] = acc;
}

// ---------------------------------------------------------------------------
// K6: fused GEMM + bias + row L2-norm + normed classifier.
//   A = [aggr | x]  (M=100000, K=256), B = [W_l ; W_r] (256x128)
//   h = A@B + b_l; out = l2norm_row(h) @ l2norm_col(W_cls)
// Persistent 148 blocks x 256 threads. Inner loop uses packed fma.rn.f32x2
// (2 MACs/lane) -> fma-pipe instruction count halved vs scalar FFMA.
// ---------------------------------------------------------------------------
#define MT 64
#define WCT_LD 130   // padded row stride for transposed W_cls (bank spread)
#define SMEM_FLOATS (256*128 + MT*256 + NUM_CLS*WCT_LD + 128 + 32)
#define SMEM_BYTES  (SMEM_FLOATS * 4)

__global__ __launch_bounds__(256, 1)
void fused_kernel(const float* __restrict__ x,
                  const float* __restrict__ W_l,
                  const float* __restrict__ b_l,
                  const float* __restrict__ W_r,
                  const float* __restrict__ W_cls,
                  float* __restrict__ out) {
    extern __shared__ float smem[];
    float* sB    = smem;                    // [256][128]
    float* sA    = sB + 256 * 128;          // [64][256]; reused as sH [64][128]
    float* sWcT  = sA + MT * 256;           // [20][130] transposed classifier W
    float* sBias = sWcT + NUM_CLS * WCT_LD; // [128]
    float* sInvC = sBias + 128;             // [20]

    const int tid = threadIdx.x;

    for (int i = tid; i < 128 * 128 / 4; i += 256) {
        reinterpret_cast<float4*>(sB)[i] =
            reinterpret_cast<const float4*>(W_l)[i];
        reinterpret_cast<float4*>(sB + 128 * 128)[i] =
            reinterpret_cast<const float4*>(W_r)[i];
    }
    // transposed classifier weights: sWcT[c][j] = W_cls[j][c]
    for (int i = tid; i < 128 * NUM_CLS; i += 256) {
        int c = i / 128, j = i - c * 128;
        sWcT[c * WCT_LD + j] = W_cls[j * NUM_CLS + c];
    }
    if (tid < 128) sBias[tid] = b_l[tid];
    __syncthreads();
    if (tid < NUM_CLS) {
        float s = 0.f;
        for (int j = 0; j < 128; ++j) { float w = sWcT[tid * WCT_LD + j]; s += w * w; }
        sInvC[tid] = 1.0f / fmaxf(sqrtf(s), 1e-12f);
    }
    __syncthreads();

    const int tn = tid & 31;   // lane -> 4-col group
    const int tm = tid >> 5;   // warp -> 8-row group
    const int numTiles = (N_NODES + MT - 1) / MT;
    const float4* sB4 = reinterpret_cast<const float4*>(sB);

    for (int tile = blockIdx.x; tile < numTiles; tile += gridDim.x) {
        const int row0 = tile * MT;

        // A tile: [64 rows][64 float4] = [aggr | x]
        for (int i = tid; i < MT * 64; i += 256) {
            int r = i >> 6, q = i & 63;
            int row = row0 + r;
            float4 v = make_float4(0.f, 0.f, 0.f, 0.f);
            if (row < N_NODES) {
                if (q < 32)
                    v = reinterpret_cast<const float4*>(g_aggr)[(size_t)row * 32 + q];
                else
                    v = reinterpret_cast<const float4*>(x)[(size_t)row * 32 + (q - 32)];
            }
            reinterpret_cast<float4*>(sA)[r * 64 + q] = v;
        }
        __syncthreads();

        // ---- GEMM main loop: packed f32x2 FMA, k stepped by 2 ----
        ull acc2[8][2];
        #pragma unroll
        for (int r = 0; r < 8; ++r) { acc2[r][0] = 0ull; acc2[r][1] = 0ull; }

        const float* sArow = sA + (tm * 8) * 256;
        #pragma unroll 4
        for (int k = 0; k < 256; k += 2) {
            float4 b0 = sB4[k * 32 + tn];
            float4 b1 = sB4[(k + 1) * 32 + tn];
            ull b0xy = pack2(b0.x, b0.y), b0zw = pack2(b0.z, b0.w);
            ull b1xy = pack2(b1.x, b1.y), b1zw = pack2(b1.z, b1.w);
            #pragma unroll
            for (int r = 0; r < 8; ++r) {
                float2 a = *reinterpret_cast<const float2*>(sArow + r * 256 + k);
                ull a0 = pack2(a.x, a.x);
                ull a1 = pack2(a.y, a.y);
                acc2[r][0] = ffma2(a0, b0xy, acc2[r][0]);
                acc2[r][1] = ffma2(a0, b0zw, acc2[r][1]);
                acc2[r][0] = ffma2(a1, b1xy, acc2[r][0]);
                acc2[r][1] = ffma2(a1, b1zw, acc2[r][1]);
            }
        }
        __syncthreads();  // done reading sA before reuse as sH

        // ---- bias + row L2 norm (warp butterfly over 128 cols) ----
        float4 bias = reinterpret_cast<const float4*>(sBias)[tn];
        #pragma unroll
        for (int r = 0; r < 8; ++r) {
            float hx, hy, hz, hw;
            unpack2(acc2[r][0], hx, hy);
            unpack2(acc2[r][1], hz, hw);
            hx += bias.x; hy += bias.y; hz += bias.z; hw += bias.w;
            float ss = hx * hx + hy * hy + hz * hz + hw * hw;
            #pragma unroll
            for (int off = 16; off; off >>= 1)
                ss += __shfl_xor_sync(0xffffffffu, ss, off);
            float inv = 1.0f / fmaxf(sqrtf(ss), 1e-12f);
            float4 h = make_float4(hx * inv, hy * inv, hz * inv, hw * inv);
            reinterpret_cast<float4*>(sA)[(tm * 8 + r) * 32 + tn] = h;
        }
        __syncthreads();

        // ---- classifier: 64 rows x 20 classes, f32x2 dot over 128 ----
        for (int o = tid; o < MT * NUM_CLS; o += 256) {
            int r = o / NUM_CLS, c = o - r * NUM_CLS;
            int row = row0 + r;
            if (row < N_NODES) {
                const ull* h2 = reinterpret_cast<const ull*>(sA + r * 128);
                const ull* w2 = reinterpret_cast<const ull*>(sWcT + c * WCT_LD);
                ull s2 = 0ull;
                #pragma unroll 16
                for (int j = 0; j < 64; ++j)
                    s2 = ffma2(h2[j], w2[j], s2);
                float lo, hi; unpack2(s2, lo, hi);
                out[(size_t)row * NUM_CLS + c] = (lo + hi) * sInvC[c];
            }
        }
        __syncthreads();
    }
}

// ---------------------------------------------------------------------------
extern "C" void kernel_launch(void* const* d_in, const int* in_sizes, int n_in,
                              void* d_out, int out_size) {
    (void)in_sizes; (void)n_in; (void)out_size;
    const float*    x     = (const float*)d_in[0];
    const unsigned* ew    = (const unsigned*)d_in[1];  // int32 or int64 words
    const float*    W_l   = (const float*)d_in[2];
    const float*    b_l   = (const float*)d_in[3];
    const float*    W_r   = (const float*)d_in[4];
    const float*    W_cls = (const float*)d_in[5];
    float*          out   = (float*)d_out;

    detect_kernel<<<1, 256>>>(ew);
    zero_kernel<<<256, 256>>>();
    count_kernel<<<(N_EDGES + 255) / 256, 256>>>(ew);
    scanA_kernel<<<SCAN_NB, 256>>>();
    scanB_kernel<<<1, 256>>>();
    scanC_kernel<<<SCAN_NB, 256>>>();
    fill_kernel<<<(N_EDGES + 255) / 256, 256>>>(ew);

    const unsigned gthreads = (unsigned)N_NODES * 32u;
    gather_kernel<<<(gthreads + 255) / 256, 256>>>(x);

    cudaFuncSetAttribute(fused_kernel,
                         cudaFuncAttributeMaxDynamicSharedMemorySize, SMEM_BYTES);
    fused_kernel<<<148, 256, SMEM_BYTES>>>(x, W_l, b_l, W_r, W_cls, out);
}

// round 7
// speedup vs baseline: 1.9378x; 1.5526x over previous
#include <cuda_runtime.h>
#include <cuda_bf16.h>
#include <math.h>

#define N_NODES  100000
#define HID      128
#define NUM_CLS  20
#define N_EDGES  625000

typedef unsigned long long u64;
typedef unsigned int u32;

// ---------------------------------------------------------------------------
// Scratch (__device__ globals; no allocation allowed)
// ---------------------------------------------------------------------------
__device__ __nv_bfloat16 g_Ahi[(size_t)N_NODES * 256];  // [aggr|x] hi halves
__device__ __nv_bfloat16 g_Alo[(size_t)N_NODES * 256];  // lo halves
__device__ __nv_bfloat16 g_Bhi[128 * 256];              // B_cat^T = [n][k]
__device__ __nv_bfloat16 g_Blo[128 * 256];
__device__ __nv_bfloat16 g_B2hi[32 * 256];              // (B_cat@Wcn)^T pad 32
__device__ __nv_bfloat16 g_B2lo[32 * 256];
__device__ float g_biasWcn[32];
__device__ int   g_cnt[N_NODES];
__device__ int   g_off[N_NODES];
__device__ int   g_cur[N_NODES];
__device__ int   g_csr[N_EDGES];
__device__ int   g_is64;

#define SCAN_B   512
#define SCAN_NB  ((N_NODES + SCAN_B - 1) / SCAN_B)   // 196
__device__ int   g_part[SCAN_NB];
__device__ int   g_base[SCAN_NB];

// ---------------------------------------------------------------------------
// helpers (sm_100-safe: ldmatrix + mma.sync only, NO tcgen05)
// ---------------------------------------------------------------------------
__device__ __forceinline__ u32 smem_u32(const void* p) {
    u32 a;
    asm("{ .reg .u64 t; cvta.to.shared.u64 t, %1; cvt.u32.u64 %0, t; }"
        : "=r"(a) : "l"(p));
    return a;
}
__device__ __forceinline__ void split_bf16(float v, unsigned short& hi, unsigned short& lo) {
    __nv_bfloat16 h = __float2bfloat16(v);
    float r = v - __bfloat162float(h);
    __nv_bfloat16 l = __float2bfloat16(r);
    hi = __bfloat16_as_ushort(h);
    lo = __bfloat16_as_ushort(l);
}
__device__ __forceinline__ void ldsm_x4(u32* r, u32 addr) {
    asm volatile("ldmatrix.sync.aligned.m8n8.x4.shared.b16 {%0,%1,%2,%3}, [%4];"
        : "=r"(r[0]), "=r"(r[1]), "=r"(r[2]), "=r"(r[3]) : "r"(addr));
}
__device__ __forceinline__ void mma_bf16(float* d, const u32* a, const u32* b) {
    asm volatile("mma.sync.aligned.m16n8k16.row.col.f32.bf16.bf16.f32 "
        "{%0,%1,%2,%3}, {%4,%5,%6,%7}, {%8,%9}, {%0,%1,%2,%3};"
        : "+f"(d[0]), "+f"(d[1]), "+f"(d[2]), "+f"(d[3])
        : "r"(a[0]), "r"(a[1]), "r"(a[2]), "r"(a[3]), "r"(b[0]), "r"(b[1]));
}

// ---------------------------------------------------------------------------
// K0: detect edge dtype (int64 vs int32 words)
// ---------------------------------------------------------------------------
__global__ void detect_kernel(const unsigned* __restrict__ ew) {
    unsigned acc = 0;
    for (int i = threadIdx.x; i < 1024; i += blockDim.x)
        acc |= ew[2 * i + 1];
    __shared__ unsigned s;
    if (threadIdx.x == 0) s = 0;
    __syncthreads();
    if (acc) atomicOr(&s, acc);
    __syncthreads();
    if (threadIdx.x == 0) g_is64 = (s == 0) ? 1 : 0;
}
__device__ __forceinline__ int edge_at(const unsigned* ew, int is64, int idx) {
    return is64 ? (int)ew[2 * idx] : (int)ew[idx];
}

__global__ void zero_kernel() {
    int i = blockIdx.x * blockDim.x + threadIdx.x;
    int stride = gridDim.x * blockDim.x;
    for (int j = i; j < N_NODES; j += stride) { g_cnt[j] = 0; g_cur[j] = 0; }
}
__global__ void count_kernel(const unsigned* __restrict__ ew) {
    int e = blockIdx.x * blockDim.x + threadIdx.x;
    if (e >= N_EDGES) return;
    int is64 = g_is64;
    atomicAdd(&g_cnt[edge_at(ew, is64, N_EDGES + e)], 1);
}
__global__ __launch_bounds__(256) void scanA_kernel() {
    __shared__ int sh[256];
    const int b = blockIdx.x, t = threadIdx.x;
    int s = 0;
    for (int i = t; i < SCAN_B; i += 256) {
        int j = b * SCAN_B + i;
        if (j < N_NODES) s += g_cnt[j];
    }
    sh[t] = s;
    __syncthreads();
    for (int off = 128; off; off >>= 1) {
        if (t < off) sh[t] += sh[t + off];
        __syncthreads();
    }
    if (t == 0) g_part[b] = sh[0];
}
__global__ __launch_bounds__(256) void scanB_kernel() {
    __shared__ int a[256];
    const int t = threadIdx.x;
    a[t] = (t < SCAN_NB) ? g_part[t] : 0;
    __syncthreads();
    for (int off = 1; off < 256; off <<= 1) {
        int v = (t >= off) ? a[t - off] : 0;
        __syncthreads();
        a[t] += v;
        __syncthreads();
    }
    if (t < SCAN_NB) g_base[t] = (t == 0) ? 0 : a[t - 1];
}
__global__ __launch_bounds__(256) void scanC_kernel() {
    __shared__ int a[256];
    const int b = blockIdx.x, t = threadIdx.x;
    const int j0 = b * SCAN_B + 2 * t;
    int c0 = (j0     < N_NODES) ? g_cnt[j0]     : 0;
    int c1 = (j0 + 1 < N_NODES) ? g_cnt[j0 + 1] : 0;
    a[t] = c0 + c1;
    __syncthreads();
    for (int off = 1; off < 256; off <<= 1) {
        int v = (t >= off) ? a[t - off] : 0;
        __syncthreads();
        a[t] += v;
        __syncthreads();
    }
    int excl = ((t == 0) ? 0 : a[t - 1]) + g_base[b];
    if (j0     < N_NODES) g_off[j0]     = excl;
    if (j0 + 1 < N_NODES) g_off[j0 + 1] = excl + c0;
}
__global__ void fill_kernel(const unsigned* __restrict__ ew) {
    int e = blockIdx.x * blockDim.x + threadIdx.x;
    if (e >= N_EDGES) return;
    int is64 = g_is64;
    int src = edge_at(ew, is64, e);
    int dst = edge_at(ew, is64, N_EDGES + e);
    g_csr[g_off[dst] + atomicAdd(&g_cur[dst], 1)] = src;
}

// ---------------------------------------------------------------------------
// gather + mean -> bf16 hi/lo into g_Ahi/g_Alo cols [0,128)
// ---------------------------------------------------------------------------
__global__ void gather_kernel(const float* __restrict__ x) {
    unsigned gtid = blockIdx.x * blockDim.x + threadIdx.x;
    unsigned n = gtid >> 5;
    int lane = threadIdx.x & 31;
    if (n >= N_NODES) return;

    int beg = g_off[n];
    int cnt = g_cnt[n];
    float4 acc = make_float4(0.f, 0.f, 0.f, 0.f);
    const float4* x4 = reinterpret_cast<const float4*>(x);

    int s = (cnt > 0) ? __ldg(&g_csr[beg]) : 0;
    for (int i = 0; i < cnt; ++i) {
        int s_next = (i + 1 < cnt) ? __ldg(&g_csr[beg + i + 1]) : 0;
        float4 v = __ldg(&x4[(size_t)s * 32 + lane]);
        acc.x += v.x; acc.y += v.y; acc.z += v.z; acc.w += v.w;
        s = s_next;
    }
    float inv = 1.0f / fmaxf((float)cnt, 1.0f);
    float vv[4] = { acc.x * inv, acc.y * inv, acc.z * inv, acc.w * inv };
    unsigned short h[4], l[4];
    #pragma unroll
    for (int i = 0; i < 4; ++i) split_bf16(vv[i], h[i], l[i]);
    uint2 uh = make_uint2((u32)h[0] | ((u32)h[1] << 16), (u32)h[2] | ((u32)h[3] << 16));
    uint2 ul = make_uint2((u32)l[0] | ((u32)l[1] << 16), (u32)l[2] | ((u32)l[3] << 16));
    size_t o = (size_t)n * 256 + 4 * lane;
    *reinterpret_cast<uint2*>(&g_Ahi[o]) = uh;
    *reinterpret_cast<uint2*>(&g_Alo[o]) = ul;
}

// ---------------------------------------------------------------------------
// convert x -> bf16 hi/lo into cols [128,256)
// ---------------------------------------------------------------------------
__global__ void convx_kernel(const float* __restrict__ x) {
    int idx = blockIdx.x * blockDim.x + threadIdx.x;
    int total = N_NODES * 32;
    int stride = gridDim.x * blockDim.x;
    for (int i = idx; i < total; i += stride) {
        int n = i >> 5, q = i & 31;
        float4 v = reinterpret_cast<const float4*>(x)[(size_t)n * 32 + q];
        float vv[4] = { v.x, v.y, v.z, v.w };
        unsigned short h[4], l[4];
        #pragma unroll
        for (int j = 0; j < 4; ++j) split_bf16(vv[j], h[j], l[j]);
        uint2 uh = make_uint2((u32)h[0] | ((u32)h[1] << 16), (u32)h[2] | ((u32)h[3] << 16));
        uint2 ul = make_uint2((u32)l[0] | ((u32)l[1] << 16), (u32)l[2] | ((u32)l[3] << 16));
        size_t o = (size_t)n * 256 + 128 + 4 * q;
        *reinterpret_cast<uint2*>(&g_Ahi[o]) = uh;
        *reinterpret_cast<uint2*>(&g_Alo[o]) = ul;
    }
}

// ---------------------------------------------------------------------------
// prep: B = W_cat^T (bf16 hi/lo), B2 = (W_cat @ Wcn)^T, biasWcn = b @ Wcn
// ---------------------------------------------------------------------------
__global__ __launch_bounds__(128)
void prep_kernel(const float* __restrict__ W_l, const float* __restrict__ b_l,
                 const float* __restrict__ W_r, const float* __restrict__ W_cls) {
    __shared__ float sW[128 * NUM_CLS];
    __shared__ float sInv[NUM_CLS];
    __shared__ float sRow[128];
    const int k = blockIdx.x, t = threadIdx.x;

    for (int i = t; i < 128 * NUM_CLS; i += 128) sW[i] = W_cls[i];
    __syncthreads();
    if (t < NUM_CLS) {
        float s = 0.f;
        for (int j = 0; j < 128; ++j) { float w = sW[j * NUM_CLS + t]; s += w * w; }
        sInv[t] = 1.0f / fmaxf(sqrtf(s), 1e-12f);
    }
    float v = (k < 128) ? W_l[k * 128 + t] : W_r[(k - 128) * 128 + t];
    sRow[t] = v;
    unsigned short h, l;
    split_bf16(v, h, l);
    g_Bhi[t * 256 + k] = __ushort_as_bfloat16(h);
    g_Blo[t * 256 + k] = __ushort_as_bfloat16(l);
    __syncthreads();

    if (t < 32) {
        float s = 0.f;
        if (t < NUM_CLS) {
            for (int j = 0; j < 128; ++j) s += sRow[j] * sW[j * NUM_CLS + t];
            s *= sInv[t];
        }
        split_bf16(s, h, l);
        g_B2hi[t * 256 + k] = __ushort_as_bfloat16(h);
        g_B2lo[t * 256 + k] = __ushort_as_bfloat16(l);
        if (k == 0) {
            float bw = 0.f;
            if (t < NUM_CLS)
                for (int j = 0; j < 128; ++j) bw += b_l[j] * sW[j * NUM_CLS + t] * sInv[t];
            g_biasWcn[t] = bw;
        }
    }
}

// ---------------------------------------------------------------------------
// MMA kernel (mma.sync bf16 split-precision, 3 passes AhBh+AhBl+AlBh).
// Per 128-row tile: D[128x160] = A[128x256] @ [B | B2]; epilogue in regs.
// B resident in smem (hi+lo, [160][256] padded to 264); A chunked k=64.
// Warp w computes rows 16w..16w+15, all 160 cols (20 m16n8 tiles).
// ---------------------------------------------------------------------------
#define B_LD  264          // bf16 elems per B row (pad 8 -> 528B stride)
#define A_LD  72           // bf16 elems per A row (pad 8 -> 144B stride)
#define SM_BIAS  0
#define SM_BWCN  512
#define SM_BH    1024
#define SM_BL    (SM_BH + 160 * B_LD * 2)
#define SM_AH    (SM_BL + 160 * B_LD * 2)
#define SM_AL    (SM_AH + 128 * A_LD * 2)
#define MMA_SMEM (SM_AL + 128 * A_LD * 2)
#define NUM_TILES ((N_NODES + 127) / 128)

__global__ __launch_bounds__(256, 1)
void mma_kernel(const float* __restrict__ b_l, float* __restrict__ out) {
    extern __shared__ char smem[];
    float* sBias = reinterpret_cast<float*>(smem + SM_BIAS);
    float* sBWcn = reinterpret_cast<float*>(smem + SM_BWCN);
    const u32 uBh = smem_u32(smem + SM_BH);
    const u32 uBl = smem_u32(smem + SM_BL);
    const u32 uAh = smem_u32(smem + SM_AH);
    const u32 uAl = smem_u32(smem + SM_AL);

    const int tid = threadIdx.x;
    const int wid = tid >> 5;
    const int lane = tid & 31;

    if (tid < 128) sBias[tid] = b_l[tid];
    if (tid < 32)  sBWcn[tid] = g_biasWcn[tid];

    // stage B (hi+lo): rows 0-127 = B_cat^T, rows 128-159 = B2^T
    for (int i = tid; i < 160 * 32; i += 256) {
        int r = i >> 5, j = i & 31;
        uint4 vh, vl;
        if (r < 128) {
            vh = *reinterpret_cast<const uint4*>(&g_Bhi[r * 256 + 8 * j]);
            vl = *reinterpret_cast<const uint4*>(&g_Blo[r * 256 + 8 * j]);
        } else {
            vh = *reinterpret_cast<const uint4*>(&g_B2hi[(r - 128) * 256 + 8 * j]);
            vl = *reinterpret_cast<const uint4*>(&g_B2lo[(r - 128) * 256 + 8 * j]);
        }
        *reinterpret_cast<uint4*>(smem + SM_BH + r * (B_LD * 2) + 16 * j) = vh;
        *reinterpret_cast<uint4*>(smem + SM_BL + r * (B_LD * 2) + 16 * j) = vl;
    }

    // per-lane fragment address components
    const int aRow = wid * 16 + (lane & 15);          // A row for ldmatrix
    const int aKoff = (lane >> 4) << 3;               // +8 for k8-15 tiles
    const int bN = (lane & 7) + ((lane >> 4) << 3);   // n within 16-group
    const int bKoff = ((lane >> 3) & 1) << 3;         // +8 for k8-15 tiles

    for (int tile = blockIdx.x; tile < NUM_TILES; tile += gridDim.x) {
        const int row0 = tile * 128;
        float acc[20][4];
        #pragma unroll
        for (int i = 0; i < 20; ++i)
            #pragma unroll
            for (int j = 0; j < 4; ++j) acc[i][j] = 0.f;

        for (int c = 0; c < 4; ++c) {                 // k chunks of 64
            __syncthreads();                           // protect prev reads
            for (int i = tid; i < 128 * 8; i += 256) {
                int r = i >> 3, j = i & 7;
                uint4 vh = make_uint4(0u,0u,0u,0u), vl = vh;
                int row = row0 + r;
                if (row < N_NODES) {
                    size_t g = (size_t)row * 256 + 64 * c + 8 * j;
                    vh = *reinterpret_cast<const uint4*>(&g_Ahi[g]);
                    vl = *reinterpret_cast<const uint4*>(&g_Alo[g]);
                }
                *reinterpret_cast<uint4*>(smem + SM_AH + r * (A_LD * 2) + 16 * j) = vh;
                *reinterpret_cast<uint4*>(smem + SM_AL + r * (A_LD * 2) + 16 * j) = vl;
            }
            __syncthreads();

            for (int pass = 0; pass < 3; ++pass) {
                u32 aBase = (pass == 2) ? uAl : uAh;
                u32 bBase = (pass == 1) ? uBl : uBh;
                for (int k16 = 0; k16 < 4; ++k16) {
                    u32 a[4];
                    ldsm_x4(a, aBase + (aRow * A_LD + k16 * 16 + aKoff) * 2);
                    const int kB = 64 * c + k16 * 16 + bKoff;
                    #pragma unroll
                    for (int ng = 0; ng < 10; ++ng) {
                        u32 b[4];
                        ldsm_x4(b, bBase + ((ng * 16 + bN) * B_LD + kB) * 2);
                        mma_bf16(acc[2 * ng],     a, b);
                        mma_bf16(acc[2 * ng + 1], a, b + 2);
                    }
                }
            }
        }

        // ---- epilogue in registers ----
        const int q = lane & 3;
        const int row0g = row0 + wid * 16 + (lane >> 2);
        const int row1g = row0g + 8;
        float ss0 = 0.f, ss1 = 0.f;
        #pragma unroll
        for (int ng = 0; ng < 8; ++ng)
            #pragma unroll
            for (int h = 0; h < 2; ++h) {
                const int i = 2 * ng + h;
                const int n = 16 * ng + 8 * h + 2 * q;
                float b0 = sBias[n], b1 = sBias[n + 1];
                float h00 = acc[i][0] + b0, h01 = acc[i][1] + b1;
                float h10 = acc[i][2] + b0, h11 = acc[i][3] + b1;
                ss0 += h00 * h00 + h01 * h01;
                ss1 += h10 * h10 + h11 * h11;
            }
        ss0 += __shfl_xor_sync(0xffffffffu, ss0, 1);
        ss0 += __shfl_xor_sync(0xffffffffu, ss0, 2);
        ss1 += __shfl_xor_sync(0xffffffffu, ss1, 1);
        ss1 += __shfl_xor_sync(0xffffffffu, ss1, 2);
        float inv0 = 1.0f / fmaxf(sqrtf(ss0), 1e-12f);
        float inv1 = 1.0f / fmaxf(sqrtf(ss1), 1e-12f);

        #pragma unroll
        for (int ng = 8; ng < 10; ++ng)
            #pragma unroll
            for (int h = 0; h < 2; ++h) {
                const int i = 2 * ng + h;
                const int n2 = 16 * (ng - 8) + 8 * h + 2 * q;
                if (n2 < 20) {
                    float w0 = sBWcn[n2], w1 = sBWcn[n2 + 1];
                    if (row0g < N_NODES) {
                        float2 v = make_float2((acc[i][0] + w0) * inv0,
                                               (acc[i][1] + w1) * inv0);
                        *reinterpret_cast<float2*>(&out[(size_t)row0g * NUM_CLS + n2]) = v;
                    }
                    if (row1g < N_NODES) {
                        float2 v = make_float2((acc[i][2] + w0) * inv1,
                                               (acc[i][3] + w1) * inv1);
                        *reinterpret_cast<float2*>(&out[(size_t)row1g * NUM_CLS + n2]) = v;
                    }
                }
            }
        // next iteration's first __syncthreads() protects smem reuse
    }
}

// ---------------------------------------------------------------------------
extern "C" void kernel_launch(void* const* d_in, const int* in_sizes, int n_in,
                              void* d_out, int out_size) {
    (void)in_sizes; (void)n_in; (void)out_size;
    const float*    x     = (const float*)d_in[0];
    const unsigned* ew    = (const unsigned*)d_in[1];
    const float*    W_l   = (const float*)d_in[2];
    const float*    b_l   = (const float*)d_in[3];
    const float*    W_r   = (const float*)d_in[4];
    const float*    W_cls = (const float*)d_in[5];
    float*          out   = (float*)d_out;

    detect_kernel<<<1, 256>>>(ew);
    zero_kernel<<<256, 256>>>();
    count_kernel<<<(N_EDGES + 255) / 256, 256>>>(ew);
    scanA_kernel<<<SCAN_NB, 256>>>();
    scanB_kernel<<<1, 256>>>();
    scanC_kernel<<<SCAN_NB, 256>>>();
    fill_kernel<<<(N_EDGES + 255) / 256, 256>>>(ew);

    prep_kernel<<<256, 128>>>(W_l, b_l, W_r, W_cls);
    convx_kernel<<<1024, 256>>>(x);

    const unsigned gthreads = (unsigned)N_NODES * 32u;
    gather_kernel<<<(gthreads + 255) / 256, 256>>>(x);

    cudaFuncSetAttribute(mma_kernel,
                         cudaFuncAttributeMaxDynamicSharedMemorySize, MMA_SMEM);
    mma_kernel<<<148, 256, MMA_SMEM>>>(b_l, out);
}

// round 8
// speedup vs baseline: 2.0797x; 1.0732x over previous
#include <cuda_runtime.h>
#include <cuda_bf16.h>
#include <math.h>

#define N_NODES  100000
#define HID      128
#define NUM_CLS  20
#define N_EDGES  625000

typedef unsigned long long u64;
typedef unsigned int u32;

// ---------------------------------------------------------------------------
// Scratch (__device__ globals; no allocation allowed)
// ---------------------------------------------------------------------------
__device__ float g_aggr[(size_t)N_NODES * HID];         // mean-aggregated (fp32)
__device__ __nv_bfloat16 g_Bhi[128 * 256];              // B_cat^T = [n][k]
__device__ __nv_bfloat16 g_Blo[128 * 256];
__device__ __nv_bfloat16 g_B2hi[32 * 256];              // (B_cat@Wcn)^T pad 32
__device__ __nv_bfloat16 g_B2lo[32 * 256];
__device__ float g_biasWcn[32];
__device__ int   g_cnt[N_NODES];
__device__ int   g_off[N_NODES];
__device__ int   g_cur[N_NODES];
__device__ int   g_csr[N_EDGES];
__device__ int   g_is64;

#define SCAN_B   512
#define SCAN_NB  ((N_NODES + SCAN_B - 1) / SCAN_B)   // 196
__device__ int   g_part[SCAN_NB];
__device__ int   g_base[SCAN_NB];

// ---------------------------------------------------------------------------
// helpers (sm_100-safe: ldmatrix + mma.sync only, NO tcgen05)
// ---------------------------------------------------------------------------
__device__ __forceinline__ u32 smem_u32(const void* p) {
    u32 a;
    asm("{ .reg .u64 t; cvta.to.shared.u64 t, %1; cvt.u32.u64 %0, t; }"
        : "=r"(a) : "l"(p));
    return a;
}
__device__ __forceinline__ void split_bf16(float v, unsigned short& hi, unsigned short& lo) {
    __nv_bfloat16 h = __float2bfloat16(v);
    float r = v - __bfloat162float(h);
    __nv_bfloat16 l = __float2bfloat16(r);
    hi = __bfloat16_as_ushort(h);
    lo = __bfloat16_as_ushort(l);
}
__device__ __forceinline__ void ldsm_x4(u32* r, u32 addr) {
    asm volatile("ldmatrix.sync.aligned.m8n8.x4.shared.b16 {%0,%1,%2,%3}, [%4];"
        : "=r"(r[0]), "=r"(r[1]), "=r"(r[2]), "=r"(r[3]) : "r"(addr));
}
__device__ __forceinline__ void mma_bf16(float* d, const u32* a, const u32* b) {
    asm volatile("mma.sync.aligned.m16n8k16.row.col.f32.bf16.bf16.f32 "
        "{%0,%1,%2,%3}, {%4,%5,%6,%7}, {%8,%9}, {%0,%1,%2,%3};"
        : "+f"(d[0]), "+f"(d[1]), "+f"(d[2]), "+f"(d[3])
        : "r"(a[0]), "r"(a[1]), "r"(a[2]), "r"(a[3]), "r"(b[0]), "r"(b[1]));
}

// ---------------------------------------------------------------------------
// K0: detect edge dtype (int64 vs int32 words)
// ---------------------------------------------------------------------------
__global__ void detect_kernel(const unsigned* __restrict__ ew) {
    unsigned acc = 0;
    for (int i = threadIdx.x; i < 1024; i += blockDim.x)
        acc |= ew[2 * i + 1];
    __shared__ unsigned s;
    if (threadIdx.x == 0) s = 0;
    __syncthreads();
    if (acc) atomicOr(&s, acc);
    __syncthreads();
    if (threadIdx.x == 0) g_is64 = (s == 0) ? 1 : 0;
}
__device__ __forceinline__ int edge_at(const unsigned* ew, int is64, int idx) {
    return is64 ? (int)ew[2 * idx] : (int)ew[idx];
}

__global__ void zero_kernel() {
    int i = blockIdx.x * blockDim.x + threadIdx.x;
    int stride = gridDim.x * blockDim.x;
    for (int j = i; j < N_NODES; j += stride) { g_cnt[j] = 0; g_cur[j] = 0; }
}
__global__ void count_kernel(const unsigned* __restrict__ ew) {
    int e = blockIdx.x * blockDim.x + threadIdx.x;
    if (e >= N_EDGES) return;
    int is64 = g_is64;
    atomicAdd(&g_cnt[edge_at(ew, is64, N_EDGES + e)], 1);
}
__global__ __launch_bounds__(256) void scanA_kernel() {
    __shared__ int sh[256];
    const int b = blockIdx.x, t = threadIdx.x;
    int s = 0;
    for (int i = t; i < SCAN_B; i += 256) {
        int j = b * SCAN_B + i;
        if (j < N_NODES) s += g_cnt[j];
    }
    sh[t] = s;
    __syncthreads();
    for (int off = 128; off; off >>= 1) {
        if (t < off) sh[t] += sh[t + off];
        __syncthreads();
    }
    if (t == 0) g_part[b] = sh[0];
}
__global__ __launch_bounds__(256) void scanB_kernel() {
    __shared__ int a[256];
    const int t = threadIdx.x;
    a[t] = (t < SCAN_NB) ? g_part[t] : 0;
    __syncthreads();
    for (int off = 1; off < 256; off <<= 1) {
        int v = (t >= off) ? a[t - off] : 0;
        __syncthreads();
        a[t] += v;
        __syncthreads();
    }
    if (t < SCAN_NB) g_base[t] = (t == 0) ? 0 : a[t - 1];
}
__global__ __launch_bounds__(256) void scanC_kernel() {
    __shared__ int a[256];
    const int b = blockIdx.x, t = threadIdx.x;
    const int j0 = b * SCAN_B + 2 * t;
    int c0 = (j0     < N_NODES) ? g_cnt[j0]     : 0;
    int c1 = (j0 + 1 < N_NODES) ? g_cnt[j0 + 1] : 0;
    a[t] = c0 + c1;
    __syncthreads();
    for (int off = 1; off < 256; off <<= 1) {
        int v = (t >= off) ? a[t - off] : 0;
        __syncthreads();
        a[t] += v;
        __syncthreads();
    }
    int excl = ((t == 0) ? 0 : a[t - 1]) + g_base[b];
    if (j0     < N_NODES) g_off[j0]     = excl;
    if (j0 + 1 < N_NODES) g_off[j0 + 1] = excl + c0;
}
__global__ void fill_kernel(const unsigned* __restrict__ ew) {
    int e = blockIdx.x * blockDim.x + threadIdx.x;
    if (e >= N_EDGES) return;
    int is64 = g_is64;
    int src = edge_at(ew, is64, e);
    int dst = edge_at(ew, is64, N_EDGES + e);
    g_csr[g_off[dst] + atomicAdd(&g_cur[dst], 1)] = src;
}

// ---------------------------------------------------------------------------
// gather + mean -> fp32 g_aggr. One warp per node, lane = float4 column.
// ---------------------------------------------------------------------------
__global__ void gather_kernel(const float* __restrict__ x) {
    unsigned gtid = blockIdx.x * blockDim.x + threadIdx.x;
    unsigned n = gtid >> 5;
    int lane = threadIdx.x & 31;
    if (n >= N_NODES) return;

    int beg = g_off[n];
    int cnt = g_cnt[n];
    float4 acc = make_float4(0.f, 0.f, 0.f, 0.f);
    const float4* x4 = reinterpret_cast<const float4*>(x);

    int s = (cnt > 0) ? __ldg(&g_csr[beg]) : 0;
    for (int i = 0; i < cnt; ++i) {
        int s_next = (i + 1 < cnt) ? __ldg(&g_csr[beg + i + 1]) : 0;
        float4 v = __ldg(&x4[(size_t)s * 32 + lane]);
        acc.x += v.x; acc.y += v.y; acc.z += v.z; acc.w += v.w;
        s = s_next;
    }
    float inv = 1.0f / fmaxf((float)cnt, 1.0f);
    acc.x *= inv; acc.y *= inv; acc.z *= inv; acc.w *= inv;
    reinterpret_cast<float4*>(g_aggr)[(size_t)n * 32 + lane] = acc;
}

// ---------------------------------------------------------------------------
// prep: B = W_cat^T (bf16 hi/lo), B2 = (W_cat @ Wcn)^T, biasWcn = b @ Wcn
// ---------------------------------------------------------------------------
__global__ __launch_bounds__(128)
void prep_kernel(const float* __restrict__ W_l, const float* __restrict__ b_l,
                 const float* __restrict__ W_r, const float* __restrict__ W_cls) {
    __shared__ float sW[128 * NUM_CLS];
    __shared__ float sInv[NUM_CLS];
    __shared__ float sRow[128];
    const int k = blockIdx.x, t = threadIdx.x;

    for (int i = t; i < 128 * NUM_CLS; i += 128) sW[i] = W_cls[i];
    __syncthreads();
    if (t < NUM_CLS) {
        float s = 0.f;
        for (int j = 0; j < 128; ++j) { float w = sW[j * NUM_CLS + t]; s += w * w; }
        sInv[t] = 1.0f / fmaxf(sqrtf(s), 1e-12f);
    }
    float v = (k < 128) ? W_l[k * 128 + t] : W_r[(k - 128) * 128 + t];
    sRow[t] = v;
    unsigned short h, l;
    split_bf16(v, h, l);
    g_Bhi[t * 256 + k] = __ushort_as_bfloat16(h);
    g_Blo[t * 256 + k] = __ushort_as_bfloat16(l);
    __syncthreads();

    if (t < 32) {
        float s = 0.f;
        if (t < NUM_CLS) {
            for (int j = 0; j < 128; ++j) s += sRow[j] * sW[j * NUM_CLS + t];
            s *= sInv[t];
        }
        split_bf16(s, h, l);
        g_B2hi[t * 256 + k] = __ushort_as_bfloat16(h);
        g_B2lo[t * 256 + k] = __ushort_as_bfloat16(l);
        if (k == 0) {
            float bw = 0.f;
            if (t < NUM_CLS)
                for (int j = 0; j < 128; ++j) bw += b_l[j] * sW[j * NUM_CLS + t] * sInv[t];
            g_biasWcn[t] = bw;
        }
    }
}

// ---------------------------------------------------------------------------
// MMA kernel (mma.sync bf16 split-precision, 3 passes AhBh+AhBl+AlBh).
// Per 128-row tile: D[128x160] = A[128x256] @ [B | B2]; epilogue in regs.
// A is read as fp32 (g_aggr for k<128, x for k>=128) and split to bf16
// hi/lo during smem staging -- no bf16 intermediate in global memory.
// ---------------------------------------------------------------------------
#define B_LD  264          // bf16 elems per B row (pad 8 -> 528B stride)
#define A_LD  72           // bf16 elems per A row (pad 8 -> 144B stride)
#define SM_BIAS  0
#define SM_BWCN  512
#define SM_BH    1024
#define SM_BL    (SM_BH + 160 * B_LD * 2)
#define SM_AH    (SM_BL + 160 * B_LD * 2)
#define SM_AL    (SM_AH + 128 * A_LD * 2)
#define MMA_SMEM (SM_AL + 128 * A_LD * 2)
#define NUM_TILES ((N_NODES + 127) / 128)

__global__ __launch_bounds__(256, 1)
void mma_kernel(const float* __restrict__ x, const float* __restrict__ b_l,
                float* __restrict__ out) {
    extern __shared__ char smem[];
    float* sBias = reinterpret_cast<float*>(smem + SM_BIAS);
    float* sBWcn = reinterpret_cast<float*>(smem + SM_BWCN);
    const u32 uBh = smem_u32(smem + SM_BH);
    const u32 uBl = smem_u32(smem + SM_BL);
    const u32 uAh = smem_u32(smem + SM_AH);
    const u32 uAl = smem_u32(smem + SM_AL);

    const int tid = threadIdx.x;
    const int wid = tid >> 5;
    const int lane = tid & 31;

    if (tid < 128) sBias[tid] = b_l[tid];
    if (tid < 32)  sBWcn[tid] = g_biasWcn[tid];

    // stage B (hi+lo): rows 0-127 = B_cat^T, rows 128-159 = B2^T
    for (int i = tid; i < 160 * 32; i += 256) {
        int r = i >> 5, j = i & 31;
        uint4 vh, vl;
        if (r < 128) {
            vh = *reinterpret_cast<const uint4*>(&g_Bhi[r * 256 + 8 * j]);
            vl = *reinterpret_cast<const uint4*>(&g_Blo[r * 256 + 8 * j]);
        } else {
            vh = *reinterpret_cast<const uint4*>(&g_B2hi[(r - 128) * 256 + 8 * j]);
            vl = *reinterpret_cast<const uint4*>(&g_B2lo[(r - 128) * 256 + 8 * j]);
        }
        *reinterpret_cast<uint4*>(smem + SM_BH + r * (B_LD * 2) + 16 * j) = vh;
        *reinterpret_cast<uint4*>(smem + SM_BL + r * (B_LD * 2) + 16 * j) = vl;
    }

    // per-lane fragment address components
    const int aRow = wid * 16 + (lane & 15);          // A row for ldmatrix
    const int aKoff = (lane >> 4) << 3;               // +8 for k8-15 tiles
    const int bN = (lane & 7) + ((lane >> 4) << 3);   // n within 16-group
    const int bKoff = ((lane >> 3) & 1) << 3;         // +8 for k8-15 tiles

    for (int tile = blockIdx.x; tile < NUM_TILES; tile += gridDim.x) {
        const int row0 = tile * 128;
        float acc[20][4];
        #pragma unroll
        for (int i = 0; i < 20; ++i)
            #pragma unroll
            for (int j = 0; j < 4; ++j) acc[i][j] = 0.f;

        for (int c = 0; c < 4; ++c) {                 // k chunks of 64
            __syncthreads();                           // protect prev reads
            // load fp32 A chunk, split to bf16 hi/lo in smem
            const float* srcBase = (c < 2) ? g_aggr : x;
            const int kb = (c & 1) * 64;               // k offset within source
            for (int i = tid; i < 128 * 8; i += 256) {
                int r = i >> 3, j = i & 7;
                float f[8];
                int row = row0 + r;
                if (row < N_NODES) {
                    const float4* p = reinterpret_cast<const float4*>(
                        srcBase + (size_t)row * 128 + kb + 8 * j);
                    float4 v0 = p[0], v1 = p[1];
                    f[0]=v0.x; f[1]=v0.y; f[2]=v0.z; f[3]=v0.w;
                    f[4]=v1.x; f[5]=v1.y; f[6]=v1.z; f[7]=v1.w;
                } else {
                    #pragma unroll
                    for (int q = 0; q < 8; ++q) f[q] = 0.f;
                }
                unsigned short h[8], l[8];
                #pragma unroll
                for (int q = 0; q < 8; ++q) split_bf16(f[q], h[q], l[q]);
                uint4 vh = make_uint4((u32)h[0] | ((u32)h[1] << 16),
                                      (u32)h[2] | ((u32)h[3] << 16),
                                      (u32)h[4] | ((u32)h[5] << 16),
                                      (u32)h[6] | ((u32)h[7] << 16));
                uint4 vl = make_uint4((u32)l[0] | ((u32)l[1] << 16),
                                      (u32)l[2] | ((u32)l[3] << 16),
                                      (u32)l[4] | ((u32)l[5] << 16),
                                      (u32)l[6] | ((u32)l[7] << 16));
                *reinterpret_cast<uint4*>(smem + SM_AH + r * (A_LD * 2) + 16 * j) = vh;
                *reinterpret_cast<uint4*>(smem + SM_AL + r * (A_LD * 2) + 16 * j) = vl;
            }
            __syncthreads();

            for (int pass = 0; pass < 3; ++pass) {
                u32 aBase = (pass == 2) ? uAl : uAh;
                u32 bBase = (pass == 1) ? uBl : uBh;
                for (int k16 = 0; k16 < 4; ++k16) {
                    u32 a[4];
                    ldsm_x4(a, aBase + (aRow * A_LD + k16 * 16 + aKoff) * 2);
                    const int kB = 64 * c + k16 * 16 + bKoff;
                    #pragma unroll
                    for (int ng = 0; ng < 10; ++ng) {
                        u32 b[4];
                        ldsm_x4(b, bBase + ((ng * 16 + bN) * B_LD + kB) * 2);
                        mma_bf16(acc[2 * ng],     a, b);
                        mma_bf16(acc[2 * ng + 1], a, b + 2);
                    }
                }
            }
        }

        // ---- epilogue in registers ----
        const int q = lane & 3;
        const int row0g = row0 + wid * 16 + (lane >> 2);
        const int row1g = row0g + 8;
        float ss0 = 0.f, ss1 = 0.f;
        #pragma unroll
        for (int ng = 0; ng < 8; ++ng)
            #pragma unroll
            for (int h = 0; h < 2; ++h) {
                const int i = 2 * ng + h;
                const int n = 16 * ng + 8 * h + 2 * q;
                float b0 = sBias[n], b1 = sBias[n + 1];
                float h00 = acc[i][0] + b0, h01 = acc[i][1] + b1;
                float h10 = acc[i][2] + b0, h11 = acc[i][3] + b1;
                ss0 += h00 * h00 + h01 * h01;
                ss1 += h10 * h10 + h11 * h11;
            }
        ss0 += __shfl_xor_sync(0xffffffffu, ss0, 1);
        ss0 += __shfl_xor_sync(0xffffffffu, ss0, 2);
        ss1 += __shfl_xor_sync(0xffffffffu, ss1, 1);
        ss1 += __shfl_xor_sync(0xffffffffu, ss1, 2);
        float inv0 = 1.0f / fmaxf(sqrtf(ss0), 1e-12f);
        float inv1 = 1.0f / fmaxf(sqrtf(ss1), 1e-12f);

        #pragma unroll
        for (int ng = 8; ng < 10; ++ng)
            #pragma unroll
            for (int h = 0; h < 2; ++h) {
                const int i = 2 * ng + h;
                const int n2 = 16 * (ng - 8) + 8 * h + 2 * q;
                if (n2 < 20) {
                    float w0 = sBWcn[n2], w1 = sBWcn[n2 + 1];
                    if (row0g < N_NODES) {
                        float2 v = make_float2((acc[i][0] + w0) * inv0,
                                               (acc[i][1] + w1) * inv0);
                        *reinterpret_cast<float2*>(&out[(size_t)row0g * NUM_CLS + n2]) = v;
                    }
                    if (row1g < N_NODES) {
                        float2 v = make_float2((acc[i][2] + w0) * inv1,
                                               (acc[i][3] + w1) * inv1);
                        *reinterpret_cast<float2*>(&out[(size_t)row1g * NUM_CLS + n2]) = v;
                    }
                }
            }
        // next iteration's first __syncthreads() protects smem reuse
    }
}

// ---------------------------------------------------------------------------
extern "C" void kernel_launch(void* const* d_in, const int* in_sizes, int n_in,
                              void* d_out, int out_size) {
    (void)in_sizes; (void)n_in; (void)out_size;
    const float*    x     = (const float*)d_in[0];
    const unsigned* ew    = (const unsigned*)d_in[1];
    const float*    W_l   = (const float*)d_in[2];
    const float*    b_l   = (const float*)d_in[3];
    const float*    W_r   = (const float*)d_in[4];
    const float*    W_cls = (const float*)d_in[5];
    float*          out   = (float*)d_out;

    detect_kernel<<<1, 256>>>(ew);
    zero_kernel<<<256, 256>>>();
    count_kernel<<<(N_EDGES + 255) / 256, 256>>>(ew);
    scanA_kernel<<<SCAN_NB, 256>>>();
    scanB_kernel<<<1, 256>>>();
    scanC_kernel<<<SCAN_NB, 256>>>();
    fill_kernel<<<(N_EDGES + 255) / 256, 256>>>(ew);

    prep_kernel<<<256, 128>>>(W_l, b_l, W_r, W_cls);

    const unsigned gthreads = (unsigned)N_NODES * 32u;
    gather_kernel<<<(gthreads + 255) / 256, 256>>>(x);

    cudaFuncSetAttribute(mma_kernel,
                         cudaFuncAttributeMaxDynamicSharedMemorySize, MMA_SMEM);
    mma_kernel<<<148, 256, MMA_SMEM>>>(x, b_l, out);
}